// round 5
// baseline (speedup 1.0000x reference)
#include <cuda_runtime.h>
#include <cuda_bf16.h>
#include <math.h>

#define NB 4
#define NM 32
#define CT 282
#define CT2 (CT*CT)
#define KTOT 24576          // 2 * 12288 floats per Gram row
#define SEG 256
#define NSEG 96             // KTOT / SEG
#define PYRTOT 16008        // per (b,m) X-pyramid complex elements
#define EPSR 1e-3f

// per-level constants
__constant__ int c_h[5]     = {2,4,8,16,32};
__constant__ int c_cnt[5]   = {192,48,24,12,6};
__constant__ int c_cbase[5] = {0,192,240,264,276};
__constant__ int c_OffC[5]  = {0,768,1536,3072,6144};   // complex offset of level block (c_l*h^2 cumsum)
__constant__ int c_LB[5]    = {0,768,1728,3744,7824};   // pyramid base per level
__constant__ int c_PS[5]    = {4,20,84,340,1364};       // pyramid size per channel of level
__constant__ int c_LO[5]    = {0,4,20,84,340};          // offset of level-l slice inside a pyramid

static const int h_h[5]     = {2,4,8,16,32};
static const int h_cnt[5]   = {192,48,24,12,6};

// scratch (device globals; no allocation)
__device__ float  d_A [NM*CT2];                    // A[m][d][c] = L[m,c,d]-L[m,d,c]
__device__ float  d_At[NM*CT2];                    // At[m][c][d] = A[m][d][c]
__device__ float  d_Spyr[NM*1364];                 // alias pyramid of s per mode
__device__ __align__(16) float2 d_Zh[NB*12288];    // per-level DFTs of z
__device__ __align__(16) float2 d_Xp[NB*NM*PYRTOT];// X = S*Zh alias pyramids
__device__ __align__(16) float  d_V [(size_t)NB*33*KTOT]; // Gram input rows (0..31 = U-hat, 32 = w-hat)
__device__ float  d_pG[(size_t)NB*NSEG*1089];      // partial Grams

struct InPtrs { const float* z[5]; const float* w[5]; };

__device__ __forceinline__ int lvl_of(int c){
    return (c<192)?0:(c<240)?1:(c<264)?2:(c<276)?3:4;
}

// ---------------------------------------------------------------- A = L^T - L
__global__ void k_prepA(const float* __restrict__ L){
    __shared__ float Ta[32][33];
    __shared__ float Tb[32][33];
    __shared__ float Tv[32][33];
    int m  = blockIdx.z;
    int c0 = blockIdx.x*32, d0 = blockIdx.y*32;
    int tx = threadIdx.x, ty = threadIdx.y;
    const float* Lm = L + (size_t)m*CT2;
    int ci = c0+ty, dj = d0+tx;
    Ta[ty][tx] = (ci<CT && dj<CT) ? Lm[ci*CT + dj] : 0.f;
    int di = d0+ty, cj = c0+tx;
    Tb[ty][tx] = (di<CT && cj<CT) ? Lm[di*CT + cj] : 0.f;
    __syncthreads();
    // A[m, d0+ty, c0+tx] = L[m, c, d] - L[m, d, c] = Ta[tx][ty] - Tb[ty][tx]
    float v = Ta[tx][ty] - Tb[ty][tx];
    if (di<CT && cj<CT) d_A[((size_t)m*CT + di)*CT + cj] = v;
    Tv[ty][tx] = v;
    __syncthreads();
    // At[m, c0+ty, d0+tx] = A[m, d0+tx, c0+ty] = Tv[tx][ty]
    if (ci<CT && dj<CT) d_At[((size_t)m*CT + ci)*CT + dj] = Tv[tx][ty];
}

// ------------------------------------------------------- s and its alias pyramid
__global__ void k_spyr(const float* __restrict__ lam){
    __shared__ float sA[1024];
    __shared__ float sB[256];
    int m = blockIdx.x;
    int tid = threadIdx.x;          // 256
    const float* lm = lam + m*1024;
    for (int t=tid; t<1024; t+=256){
        int p = t>>5, q = t&31;
        float v = lm[t] - lm[(((32-p)&31)<<5) + ((32-q)&31)];
        sA[t] = v;
        d_Spyr[m*1364 + 340 + t] = v;
    }
    float* src = sA; float* dst = sB;
    int hs = 32;
    for (int k=0; k<4; ++k){
        __syncthreads();
        int hn = hs>>1;
        int off = c_LO[3-k];        // 84,20,4,0
        for (int t=tid; t<hn*hn; t+=256){
            int p = t/hn, q = t-p*hn;
            float v = src[p*hs+q] + src[(p+hn)*hs+q]
                    + src[p*hs+q+hn] + src[(p+hn)*hs+q+hn];
            dst[t] = v;
            d_Spyr[m*1364 + off + t] = v;
        }
        float* tmp = src; src = dst; dst = tmp;
        hs = hn;
    }
}

// ------------------------------------------- small 2D DFTs of z (and w -> V row 32)
__global__ void k_dft(InPtrs P){
    __shared__ float sIn[1024];
    __shared__ float tRe[1024];
    __shared__ float tIm[1024];
    int c = blockIdx.x, b = blockIdx.y, isw = blockIdx.z;
    int l = lvl_of(c);
    int h = c_h[l], h2 = h*h;
    int dl = c - c_cbase[l];
    const float* in = (isw ? P.w[l] : P.z[l]) + (size_t)(b*c_cnt[l] + dl)*h2;
    int tid = threadIdx.x;          // 128
    for (int t=tid; t<h2; t+=128) sIn[t] = in[t];
    __syncthreads();
    float w0 = -6.283185307179586f / (float)h;
    // pass 1: tmp[p][x] = sum_y in[y][x] e^{-2pi i p y / h}
    for (int t=tid; t<h2; t+=128){
        int p = t/h, x = t-p*h;
        float ar=0.f, ai=0.f;
        for (int y=0; y<h; ++y){
            int k = (p*y) % h;
            float sn, cn; __sincosf(w0*(float)k, &sn, &cn);
            float v = sIn[y*h+x];
            ar += v*cn; ai += v*sn;
        }
        tRe[t]=ar; tIm[t]=ai;
    }
    __syncthreads();
    // pass 2: out[p][q] = sum_x tmp[p][x] e^{-2pi i q x / h}
    for (int t=tid; t<h2; t+=128){
        int p = t/h, q = t-p*h;
        float ar=0.f, ai=0.f;
        for (int x=0; x<h; ++x){
            int k = (q*x) % h;
            float sn, cn; __sincosf(w0*(float)k, &sn, &cn);
            float re = tRe[p*h+x], im = tIm[p*h+x];
            ar += re*cn - im*sn;
            ai += re*sn + im*cn;
        }
        int kk = c_OffC[l] + dl*h2 + t;
        if (!isw){
            d_Zh[b*12288 + kk] = make_float2(ar, ai);
        } else {
            float inv = 1.0f/(float)h;
            float* vrow = d_V + ((size_t)(b*33+32))*KTOT;
            vrow[2*kk  ] =  ai*inv;   // Re(i * U * conj(W)) pairing
            vrow[2*kk+1] = -ar*inv;
        }
    }
}

// ------------------------------------------------- X = S_l * Zh, alias pyramid
__global__ void k_xpyr(){
    __shared__ float2 bA[1024];
    __shared__ float2 bB[256];
    int c = blockIdx.x, m = blockIdx.y, b = blockIdx.z;
    int l = lvl_of(c);
    int h = c_h[l], h2 = h*h;
    int dl = c - c_cbase[l];
    int tid = threadIdx.x;          // 128
    const float2* Z = d_Zh + b*12288 + c_OffC[l] + dl*h2;
    const float*  S = d_Spyr + m*1364 + c_LO[l];
    size_t xbase = ((size_t)(b*NM+m))*PYRTOT + c_LB[l] + (size_t)c_PS[l]*dl;
    for (int t=tid; t<h2; t+=128){
        float2 z = Z[t]; float s = S[t];
        float2 v = make_float2(s*z.x, s*z.y);
        bA[t] = v;
        d_Xp[xbase + c_LO[l] + t] = v;
    }
    float2* src = bA; float2* dst = bB;
    int hs = h;
    for (int lt=l-1; lt>=0; --lt){
        __syncthreads();
        int hn = hs>>1;
        for (int t=tid; t<hn*hn; t+=128){
            int p = t/hn, q = t-p*hn;
            float2 a0 = src[p*hs+q],      a1 = src[(p+hn)*hs+q];
            float2 a2 = src[p*hs+q+hn],   a3 = src[(p+hn)*hs+q+hn];
            float2 v = make_float2(a0.x+a1.x+a2.x+a3.x, a0.y+a1.y+a2.y+a3.y);
            dst[t] = v;
            d_Xp[xbase + c_LO[lt] + t] = v;
        }
        float2* tmp = src; src = dst; dst = tmp;
        hs = hn;
    }
}

// ------------------------------------------------- main mixing GEMM per level
__global__ void k_gemm(int l){
    int tid = threadIdx.x;
    int m = blockIdx.y, b = blockIdx.z;
    int h = c_h[l], h2 = h*h;
    int groups = h2 >> 2;
    int slots = c_cnt[l]*groups;
    int slot = blockIdx.x*blockDim.x + tid;
    if (slot >= slots) return;
    int d_local = slot / groups;
    int pg = slot - d_local*groups;
    int pq0 = pg*4;
    int dglob = c_cbase[l] + d_local;

    int p[4], q[4];
    #pragma unroll
    for (int j=0;j<4;++j){ int pq = pq0+j; p[j] = pq/h; q[j] = pq - p[j]*h; }

    float aR[4]={0,0,0,0}, aI[4]={0,0,0,0};
    float cR[4]={0,0,0,0}, cI[4]={0,0,0,0};

    size_t bm = ((size_t)(b*NM+m))*PYRTOT;
    const float* Arow  = d_A  + ((size_t)(m*CT + dglob))*CT;
    const float* Atbas = d_At + (size_t)m*CT2;
    bool useAt = (groups < 32);

    // fine / equal resolution sources: read X pyramid at level l
    for (int ls=l; ls<5; ++ls){
        const float2* xp = d_Xp + bm + c_LB[ls] + c_LO[l] + pq0;
        int cb = c_cbase[ls], cnt = c_cnt[ls], ps = c_PS[ls];
        for (int dl=0; dl<cnt; ++dl){
            float a = useAt ? Atbas[(size_t)(cb+dl)*CT + dglob] : Arow[cb+dl];
            float4 x01 = *(const float4*)(xp);
            float4 x23 = *(const float4*)(xp+2);
            aR[0] += a*x01.x; aI[0] += a*x01.y;
            aR[1] += a*x01.z; aI[1] += a*x01.w;
            aR[2] += a*x23.x; aI[2] += a*x23.y;
            aR[3] += a*x23.z; aI[3] += a*x23.w;
            xp += ps;
        }
    }
    // coarse sources (h_src < h_l): accumulate A*Zh, multiply by S_l at end
    for (int ls=0; ls<l; ++ls){
        int hs = c_h[ls];
        int idx[4];
        #pragma unroll
        for (int j=0;j<4;++j) idx[j] = (p[j]&(hs-1))*hs + (q[j]&(hs-1));
        const float2* zp = d_Zh + b*12288 + c_OffC[ls];
        int cb = c_cbase[ls], cnt = c_cnt[ls], ss = hs*hs;
        for (int dl=0; dl<cnt; ++dl){
            float a = useAt ? Atbas[(size_t)(cb+dl)*CT + dglob] : Arow[cb+dl];
            #pragma unroll
            for (int j=0;j<4;++j){
                float2 z = zp[idx[j]];
                cR[j] += a*z.x; cI[j] += a*z.y;
            }
            zp += ss;
        }
    }
    const float* S = d_Spyr + m*1364 + c_LO[l];
    float scale = (float)h * (1.0f/1024.0f);
    float* vrow = d_V + ((size_t)(b*33+m))*KTOT + 2*(c_OffC[l] + d_local*h2 + pq0);
    float4 o0, o1;
    {
        float s0=S[pq0+0], s1=S[pq0+1], s2=S[pq0+2], s3=S[pq0+3];
        o0.x = scale*(aR[0]+s0*cR[0]); o0.y = scale*(aI[0]+s0*cI[0]);
        o0.z = scale*(aR[1]+s1*cR[1]); o0.w = scale*(aI[1]+s1*cI[1]);
        o1.x = scale*(aR[2]+s2*cR[2]); o1.y = scale*(aI[2]+s2*cI[2]);
        o1.z = scale*(aR[3]+s3*cR[3]); o1.w = scale*(aI[3]+s3*cI[3]);
    }
    *(float4*)(vrow)   = o0;
    *(float4*)(vrow+4) = o1;
}

// ------------------------------------------------- segmented 33x33 Gram
__global__ void k_gram(){
    __shared__ float sm[33*257];
    int seg = blockIdx.x, b = blockIdx.y;
    int tid = threadIdx.x;          // 256
    const float* Vb = d_V + (size_t)b*33*KTOT + seg*SEG;
    for (int r=0; r<33; ++r) sm[r*257+tid] = Vb[(size_t)r*KTOT + tid];
    __syncthreads();
    for (int pair=tid; pair<1089; pair+=256){
        int i = pair/33, j = pair-33*i;
        const float* ri = sm + i*257;
        const float* rj = sm + j*257;
        float acc = 0.f;
        #pragma unroll 8
        for (int k=0; k<SEG; ++k) acc += ri[k]*rj[k];
        d_pG[((size_t)(b*NSEG+seg))*1089 + pair] = acc;
    }
}

// ------------------------------------------------- reduce + stats + Cholesky
__global__ void k_final(float* __restrict__ out){
    __shared__ float G[1089];
    __shared__ float Mch[32][33];
    __shared__ float sc0;
    int b = blockIdx.x;
    int tid = threadIdx.x;          // 256
    for (int pair=tid; pair<1089; pair+=256){
        float acc = 0.f;
        for (int s=0; s<NSEG; ++s) acc += d_pG[((size_t)(b*NSEG+s))*1089 + pair];
        G[pair] = acc;
    }
    __syncthreads();
    if (tid < 32){
        float dg = G[tid*33+tid];
        for (int o=16;o>0;o>>=1) dg += __shfl_down_sync(0xffffffffu, dg, o);
        if (tid==0){
            float var = dg * (1.0f/32.0f);
            if (var < 1e-6f) var = 1e-6f;
            sc0 = var;
        }
    }
    __syncthreads();
    float var = sc0;
    float inv_var = 1.0f/var;
    for (int t=tid; t<1024; t+=256){
        int i = t>>5, j = t&31;
        Mch[i][j] = G[i*33+j]*inv_var + ((i==j)?EPSR:0.f);
    }
    __syncthreads();
    for (int k=0; k<32; ++k){
        if (tid==0) Mch[k][k] = sqrtf(Mch[k][k]);
        __syncthreads();
        if (tid>k && tid<32) Mch[tid][k] /= Mch[k][k];
        __syncthreads();
        if (tid>k && tid<32){
            float lik = Mch[tid][k];
            for (int j=k+1; j<=tid; ++j) Mch[tid][j] -= lik*Mch[j][k];
        }
        __syncthreads();
    }
    if (tid < 32){
        float ld  = 2.0f*logf(Mch[tid][tid]);
        float zw  = G[tid*33+32];
        float zw2 = zw*zw;
        for (int o=16;o>0;o>>=1){
            ld  += __shfl_down_sync(0xffffffffu, ld,  o);
            zw2 += __shfl_down_sync(0xffffffffu, zw2, o);
        }
        if (tid==0){
            float trace = EPSR*G[32*33+32] + zw2*inv_var;
            out[b] = 0.5f*(ld - trace);
        }
    }
}

// ----------------------------------------------------------------------------
extern "C" void kernel_launch(void* const* d_in, const int* in_sizes, int n_in,
                              void* d_out, int out_size){
    (void)n_in; (void)out_size;
    InPtrs P;
    const float* L; const float* lam;
    if (in_sizes[0] > 1000000){
        // alphabetical: L, lam, w0..w4, z0..z4
        L   = (const float*)d_in[0];
        lam = (const float*)d_in[1];
        for (int l=0;l<5;++l){ P.w[l] = (const float*)d_in[2+l]; P.z[l] = (const float*)d_in[7+l]; }
    } else if (in_sizes[2] == 6144){
        // grouped: z0..z4, w0..w4, L, lam
        for (int l=0;l<5;++l){ P.z[l] = (const float*)d_in[l]; P.w[l] = (const float*)d_in[5+l]; }
        L   = (const float*)d_in[10];
        lam = (const float*)d_in[11];
    } else {
        // dict insertion order: z0,w0,z1,w1,...,L,lam
        for (int l=0;l<5;++l){ P.z[l] = (const float*)d_in[2*l]; P.w[l] = (const float*)d_in[2*l+1]; }
        L   = (const float*)d_in[10];
        lam = (const float*)d_in[11];
    }
    float* out = (float*)d_out;

    dim3 tA(32,32), gA(9,9,NM);
    k_prepA<<<gA, tA>>>(L);
    k_spyr<<<NM, 256>>>(lam);
    k_dft<<<dim3(CT, NB, 2), 128>>>(P);
    k_xpyr<<<dim3(CT, NM, NB), 128>>>();
    for (int l=0; l<5; ++l){
        int h2 = h_h[l]*h_h[l];
        int slots = h_cnt[l]*(h2/4);
        int gx = (slots + 127)/128;
        k_gemm<<<dim3(gx, NM, NB), 128>>>(l);
    }
    k_gram<<<dim3(NSEG, NB), 256>>>();
    k_final<<<NB, 256>>>(out);
}

// round 6
// speedup vs baseline: 2.5093x; 2.5093x over previous
#include <cuda_runtime.h>
#include <cuda_bf16.h>
#include <math.h>

#define NB 4
#define NM 32
#define CT 282
#define CT2 (CT*CT)
#define KTOT 24576          // 2 * 12288 floats per Gram row
#define SEG 256
#define NSEG 96
#define EPSR 1e-3f

#define SXP_N 16008         // X-pyramid complex elements per (b,m)
#define SC_N  3720          // C-table complex elements per (b,m)
#define SMEM_MAIN ((SXP_N + SC_N) * 8 + 1364 * 4)   // 163280 bytes

// per-level constants
__constant__ int c_h[5]     = {2,4,8,16,32};
__constant__ int c_cnt[5]   = {192,48,24,12,6};
__constant__ int c_cbase[6] = {0,192,240,264,276,282};
__constant__ int c_OffC[5]  = {0,768,1536,3072,6144};   // complex offset of level block in Zh
__constant__ int c_LB[5]    = {0,768,1728,3744,7824};   // pyramid base per level
__constant__ int c_PS[5]    = {4,20,84,340,1364};       // pyramid size per channel of level
__constant__ int c_LO[5]    = {0,4,20,84,340};          // offset of level-l slice inside a pyramid
__constant__ int c_Cb[4]    = {0,360,1032,2184};        // C-table base per source level

// scratch (device globals; no allocation)
__device__ float  d_A [NM*CT2];                    // A[m][d][c] = L[m,c,d]-L[m,d,c]
__device__ float  d_Spyr[NM*1364];                 // alias pyramid of s per mode
__device__ __align__(16) float2 d_Zh[NB*12288];    // per-level DFTs of z
__device__ __align__(16) float  d_V [(size_t)NB*33*KTOT]; // Gram rows (0..31 = U-hat, 32 = w-hat)
__device__ float  d_pG[(size_t)NB*NSEG*1089];      // partial Grams
__device__ float  d_G [NB*1089];                   // reduced Grams

struct InPtrs { const float* z[5]; const float* w[5]; };

__device__ __forceinline__ int lvl_of(int c){
    return (c<192)?0:(c<240)?1:(c<264)?2:(c<276)?3:4;
}

// ---------------------------------------------------------------- A = L^T - L
__global__ void k_prepA(const float* __restrict__ L){
    __shared__ float Ta[32][33];
    int m  = blockIdx.z;
    int c0 = blockIdx.x*32, d0 = blockIdx.y*32;
    int tx = threadIdx.x, ty = threadIdx.y;
    const float* Lm = L + (size_t)m*CT2;
    int ci = c0+ty, dj = d0+tx;
    Ta[ty][tx] = (ci<CT && dj<CT) ? Lm[ci*CT + dj] : 0.f;
    __syncthreads();
    int di = d0+ty, cj = c0+tx;
    if (di<CT && cj<CT){
        // A[m, d, c] = L[m, c, d] - L[m, d, c]
        d_A[((size_t)m*CT + di)*CT + cj] = Ta[tx][ty] - Lm[di*CT + cj];
    }
}

// ------------------------------------------------------- s and its alias pyramid
__global__ void k_spyr(const float* __restrict__ lam){
    __shared__ float sA[1024];
    __shared__ float sB[256];
    int m = blockIdx.x;
    int tid = threadIdx.x;          // 256
    const float* lm = lam + m*1024;
    for (int t=tid; t<1024; t+=256){
        int p = t>>5, q = t&31;
        float v = lm[t] - lm[(((32-p)&31)<<5) + ((32-q)&31)];
        sA[t] = v;
        d_Spyr[m*1364 + 340 + t] = v;
    }
    float* src = sA; float* dst = sB;
    int hs = 32;
    for (int k=0; k<4; ++k){
        __syncthreads();
        int hn = hs>>1;
        int off = c_LO[3-k];        // 84,20,4,0
        for (int t=tid; t<hn*hn; t+=256){
            int p = t/hn, q = t-p*hn;
            float v = src[p*hs+q] + src[(p+hn)*hs+q]
                    + src[p*hs+q+hn] + src[(p+hn)*hs+q+hn];
            dst[t] = v;
            d_Spyr[m*1364 + off + t] = v;
        }
        float* tmp = src; src = dst; dst = tmp;
        hs = hn;
    }
}

// ------------------------------------------- small 2D DFTs of z (and w -> V row 32)
__global__ void k_dft(InPtrs P){
    __shared__ float sIn[1024];
    __shared__ float tRe[1024];
    __shared__ float tIm[1024];
    __shared__ float2 tw[32];
    int c = blockIdx.x, b = blockIdx.y, isw = blockIdx.z;
    int l = lvl_of(c);
    int h = c_h[l], h2 = h*h, hm = h-1;
    int dl = c - c_cbase[l];
    const float* in = (isw ? P.w[l] : P.z[l]) + (size_t)(b*c_cnt[l] + dl)*h2;
    int tid = threadIdx.x;          // 128
    if (tid < h){
        float sn, cn; __sincosf(-6.283185307179586f*(float)tid/(float)h, &sn, &cn);
        tw[tid] = make_float2(cn, sn);
    }
    for (int t=tid; t<h2; t+=128) sIn[t] = in[t];
    __syncthreads();
    // pass 1: tmp[p][x] = sum_y in[y][x] e^{-2pi i p y / h}
    for (int t=tid; t<h2; t+=128){
        int p = t/h, x = t-p*h;
        float ar=0.f, ai=0.f;
        for (int y=0; y<h; ++y){
            float2 e = tw[(p*y)&hm];
            float v = sIn[y*h+x];
            ar += v*e.x; ai += v*e.y;
        }
        tRe[t]=ar; tIm[t]=ai;
    }
    __syncthreads();
    // pass 2: out[p][q] = sum_x tmp[p][x] e^{-2pi i q x / h}
    for (int t=tid; t<h2; t+=128){
        int p = t/h, q = t-p*h;
        float ar=0.f, ai=0.f;
        for (int x=0; x<h; ++x){
            float2 e = tw[(q*x)&hm];
            float re = tRe[p*h+x], im = tIm[p*h+x];
            ar += re*e.x - im*e.y;
            ai += re*e.y + im*e.x;
        }
        int kk = c_OffC[l] + dl*h2 + t;
        if (!isw){
            d_Zh[b*12288 + kk] = make_float2(ar, ai);
        } else {
            float inv = 1.0f/(float)h;
            float* vrow = d_V + ((size_t)(b*33+32))*KTOT;
            vrow[2*kk  ] =  ai*inv;
            vrow[2*kk+1] = -ar*inv;
        }
    }
}

// ====================== fused per-(b,m) vector-field kernel ======================
__global__ void __launch_bounds__(256) k_main(){
    extern __shared__ float smraw[];
    float2* sXp = (float2*)smraw;              // [SXP_N]
    float2* sC  = sXp + SXP_N;                 // [SC_N]
    float*  sS  = (float*)(sC + SC_N);         // [1364]
    int m = blockIdx.x, b = blockIdx.y;
    int tid = threadIdx.x;

    for (int t=tid; t<1364; t+=256) sS[t] = d_Spyr[m*1364 + t];
    __syncthreads();

    const float2* Zb = d_Zh + b*12288;

    // ---- phase 1a: finest slices  sXp = S (x) Zh
    for (int f=tid; f<12288; f+=256){
        int l, rel;
        if (f<768){l=0;rel=f;} else if (f<1536){l=1;rel=f-768;}
        else if (f<3072){l=2;rel=f-1536;} else if (f<6144){l=3;rel=f-3072;}
        else {l=4;rel=f-6144;}
        int h2 = c_h[l]*c_h[l];
        int dl = rel/h2, pt = rel-dl*h2;
        float s = sS[c_LO[l]+pt];
        float2 z = Zb[f];
        sXp[c_LB[l] + c_PS[l]*dl + c_LO[l] + pt] = make_float2(s*z.x, s*z.y);
    }
    __syncthreads();

    // ---- phase 1b: alias pyramid, 4 steps
    for (int step=1; step<=4; ++step){
        for (int lc=step; lc<=4; ++lc){
            int lt = lc-step;
            int hn = c_h[lt], hsrc = hn*2, hh = hn*hn;
            int n = c_cnt[lc]*hh;
            for (int t=tid; t<n; t+=256){
                int dl = t/hh, pt = t-dl*hh;
                int p = pt/hn, q = pt-p*hn;
                float2* bch = sXp + c_LB[lc] + c_PS[lc]*dl;
                const float2* src = bch + c_LO[lt+1];
                float2 a0=src[p*hsrc+q],    a1=src[(p+hn)*hsrc+q];
                float2 a2=src[p*hsrc+q+hn], a3=src[(p+hn)*hsrc+q+hn];
                bch[c_LO[lt]+pt] = make_float2(a0.x+a1.x+a2.x+a3.x, a0.y+a1.y+a2.y+a3.y);
            }
        }
        __syncthreads();
    }

    // ---- phase 2: coarse residue table  C[d, ls, r] = sum_c A[d,c] Zh_c[r]
    // items: (ls, di, rtile4): counts {90,168,288,384}, cum {90,258,546,930}
    for (int it=tid; it<930; it+=256){
        int ls, rem;
        if (it<90){ls=0;rem=it;} else if (it<258){ls=1;rem=it-90;}
        else if (it<546){ls=2;rem=it-258;} else {ls=3;rem=it-546;}
        int hs=c_h[ls], hh=hs*hs, nrt=hh>>2;
        int di = rem/nrt, rt = rem-di*nrt;
        int r0 = rt*4;
        int dg = c_cbase[ls+1] + di;
        const float* Ar = d_A + ((size_t)m*CT + dg)*CT + c_cbase[ls];
        const float2* Zp = Zb + c_OffC[ls] + r0;
        int cnt = c_cnt[ls];
        float xr0=0,xi0=0,xr1=0,xi1=0,xr2=0,xi2=0,xr3=0,xi3=0;
        for (int c=0; c<cnt; ++c){
            float a = __ldg(Ar + c);
            float4 z01 = __ldg((const float4*)(Zp));
            float4 z23 = __ldg((const float4*)(Zp+2));
            xr0 += a*z01.x; xi0 += a*z01.y;
            xr1 += a*z01.z; xi1 += a*z01.w;
            xr2 += a*z23.x; xi2 += a*z23.y;
            xr3 += a*z23.z; xi3 += a*z23.w;
            Zp += hh;
        }
        float2* Cp = sC + c_Cb[ls] + di*hh + r0;
        Cp[0]=make_float2(xr0,xi0); Cp[1]=make_float2(xr1,xi1);
        Cp[2]=make_float2(xr2,xi2); Cp[3]=make_float2(xr3,xi3);
    }
    __syncthreads();

    // ---- phase 3: fine GEMM (from sXp) + coarse lookup (sC), 2d x 4k tiles
    // items: l0:96, l1:96, l2:192, l3:384, l4:768 -> 1536
    float* vbase = d_V + ((size_t)(b*33+m))*KTOT;
    for (int it=tid; it<1536; it+=256){
        int l, rem;
        if (it<96){l=0;rem=it;} else if (it<192){l=1;rem=it-96;}
        else if (it<384){l=2;rem=it-192;} else if (it<768){l=3;rem=it-384;}
        else {l=4;rem=it-768;}
        int h=c_h[l], h2=h*h, nkt=h2>>2, hm=h-1;
        int dp = rem/nkt, kt = rem-dp*nkt;
        int k0 = kt*4;
        int d0 = c_cbase[l] + 2*dp;

        float f0r0=0,f0i0=0,f0r1=0,f0i1=0,f0r2=0,f0i2=0,f0r3=0,f0i3=0;
        float f1r0=0,f1i0=0,f1r1=0,f1i1=0,f1r2=0,f1i2=0,f1r3=0,f1i3=0;

        const float* A0 = d_A + ((size_t)m*CT + d0)*CT;
        const float* A1 = A0 + CT;
        for (int lc=l; lc<=4; ++lc){
            const float2* xp = sXp + c_LB[lc] + c_LO[l] + k0;
            int cb=c_cbase[lc], cnt=c_cnt[lc], ps=c_PS[lc];
            for (int dl=0; dl<cnt; ++dl){
                float a0 = __ldg(A0 + cb + dl);
                float a1 = __ldg(A1 + cb + dl);
                float4 x01 = *(const float4*)(xp);
                float4 x23 = *(const float4*)(xp+2);
                f0r0 += a0*x01.x; f0i0 += a0*x01.y;
                f0r1 += a0*x01.z; f0i1 += a0*x01.w;
                f0r2 += a0*x23.x; f0i2 += a0*x23.y;
                f0r3 += a0*x23.z; f0i3 += a0*x23.w;
                f1r0 += a1*x01.x; f1i0 += a1*x01.y;
                f1r1 += a1*x01.z; f1i1 += a1*x01.w;
                f1r2 += a1*x23.x; f1i2 += a1*x23.y;
                f1r3 += a1*x23.z; f1i3 += a1*x23.w;
                xp += ps;
            }
        }

        float c0r[4]={0,0,0,0}, c0i[4]={0,0,0,0};
        float c1r[4]={0,0,0,0}, c1i[4]={0,0,0,0};
        int pp[4], qq[4];
        #pragma unroll
        for (int j=0;j<4;++j){ int k=k0+j; pp[j]=k/h; qq[j]=k&hm; }
        for (int ls=0; ls<l; ++ls){
            int hs=c_h[ls], hh=hs*hs, hsm=hs-1;
            const float2* Cp = sC + c_Cb[ls] + (d0 - c_cbase[ls+1])*hh;
            #pragma unroll
            for (int j=0;j<4;++j){
                int r = (pp[j]&hsm)*hs + (qq[j]&hsm);
                float2 v0 = Cp[r], v1 = Cp[hh+r];
                c0r[j]+=v0.x; c0i[j]+=v0.y;
                c1r[j]+=v1.x; c1i[j]+=v1.y;
            }
        }

        float scale = (float)h * (1.0f/1024.0f);
        const float* Sl = sS + c_LO[l] + k0;
        float s0=Sl[0], s1=Sl[1], s2=Sl[2], s3=Sl[3];
        {
            float* vp = vbase + 2*(c_OffC[l] + (2*dp)*h2 + k0);
            float4 o0, o1;
            o0.x = scale*(f0r0 + s0*c0r[0]); o0.y = scale*(f0i0 + s0*c0i[0]);
            o0.z = scale*(f0r1 + s1*c0r[1]); o0.w = scale*(f0i1 + s1*c0i[1]);
            o1.x = scale*(f0r2 + s2*c0r[2]); o1.y = scale*(f0i2 + s2*c0i[2]);
            o1.z = scale*(f0r3 + s3*c0r[3]); o1.w = scale*(f0i3 + s3*c0i[3]);
            *(float4*)(vp)   = o0;
            *(float4*)(vp+4) = o1;
        }
        {
            float* vp = vbase + 2*(c_OffC[l] + (2*dp+1)*h2 + k0);
            float4 o0, o1;
            o0.x = scale*(f1r0 + s0*c1r[0]); o0.y = scale*(f1i0 + s0*c1i[0]);
            o0.z = scale*(f1r1 + s1*c1r[1]); o0.w = scale*(f1i1 + s1*c1i[1]);
            o1.x = scale*(f1r2 + s2*c1r[2]); o1.y = scale*(f1i2 + s2*c1i[2]);
            o1.z = scale*(f1r3 + s3*c1r[3]); o1.w = scale*(f1i3 + s3*c1i[3]);
            *(float4*)(vp)   = o0;
            *(float4*)(vp+4) = o1;
        }
    }
}

// ------------------------------------------------- segmented 33x33 Gram, 2x2 tiled
__global__ void __launch_bounds__(256) k_gram(){
    __shared__ float sm[34*257];
    int seg = blockIdx.x, b = blockIdx.y;
    int tid = threadIdx.x;          // 256
    const float* Vb = d_V + (size_t)b*33*KTOT + seg*SEG;
    for (int r=0; r<33; ++r) sm[r*257+tid] = Vb[(size_t)r*KTOT + tid];
    sm[33*257+tid] = 0.f;
    __syncthreads();
    float* out = d_pG + ((size_t)(b*NSEG+seg))*1089;
    for (int t=tid; t<289; t+=256){
        int ti = t/17, tj = t-17*ti;
        const float* r0 = sm + (2*ti)*257;
        const float* r1 = r0 + 257;
        const float* q0 = sm + (2*tj)*257;
        const float* q1 = q0 + 257;
        float a00=0,a01=0,a10=0,a11=0;
        #pragma unroll 4
        for (int k=0; k<SEG; ++k){
            float x0=r0[k], x1=r1[k], y0=q0[k], y1=q1[k];
            a00 += x0*y0; a01 += x0*y1;
            a10 += x1*y0; a11 += x1*y1;
        }
        int i0=2*ti, j0=2*tj;
        if (j0<33){
            if (i0<33)   out[i0*33+j0]     = a00;
            if (i0+1<33) out[(i0+1)*33+j0] = a10;
        }
        if (j0+1<33){
            if (i0<33)   out[i0*33+j0+1]     = a01;
            if (i0+1<33) out[(i0+1)*33+j0+1] = a11;
        }
    }
}

// ------------------------------------------------- parallel partial-Gram reduce
__global__ void k_reduce(){
    int idx = blockIdx.x*256 + threadIdx.x;
    if (idx >= NB*1089) return;
    int b = idx/1089, pair = idx - 1089*b;
    float acc = 0.f;
    #pragma unroll 8
    for (int s=0; s<NSEG; ++s) acc += d_pG[((size_t)(b*NSEG+s))*1089 + pair];
    d_G[idx] = acc;
}

// ------------------------------------------------- stats + Cholesky + logdet
__global__ void k_final(float* __restrict__ out){
    __shared__ float G[1089];
    __shared__ float Mch[32][33];
    __shared__ float sc0;
    int b = blockIdx.x;
    int tid = threadIdx.x;          // 256
    for (int pair=tid; pair<1089; pair+=256) G[pair] = d_G[b*1089 + pair];
    __syncthreads();
    if (tid < 32){
        float dg = G[tid*33+tid];
        for (int o=16;o>0;o>>=1) dg += __shfl_down_sync(0xffffffffu, dg, o);
        if (tid==0){
            float var = dg * (1.0f/32.0f);
            if (var < 1e-6f) var = 1e-6f;
            sc0 = var;
        }
    }
    __syncthreads();
    float var = sc0;
    float inv_var = 1.0f/var;
    for (int t=tid; t<1024; t+=256){
        int i = t>>5, j = t&31;
        Mch[i][j] = G[i*33+j]*inv_var + ((i==j)?EPSR:0.f);
    }
    __syncthreads();
    for (int k=0; k<32; ++k){
        if (tid==0) Mch[k][k] = sqrtf(Mch[k][k]);
        __syncthreads();
        if (tid>k && tid<32) Mch[tid][k] /= Mch[k][k];
        __syncthreads();
        if (tid>k && tid<32){
            float lik = Mch[tid][k];
            for (int j=k+1; j<=tid; ++j) Mch[tid][j] -= lik*Mch[j][k];
        }
        __syncthreads();
    }
    if (tid < 32){
        float ld  = 2.0f*logf(Mch[tid][tid]);
        float zw  = G[tid*33+32];
        float zw2 = zw*zw;
        for (int o=16;o>0;o>>=1){
            ld  += __shfl_down_sync(0xffffffffu, ld,  o);
            zw2 += __shfl_down_sync(0xffffffffu, zw2, o);
        }
        if (tid==0){
            float trace = EPSR*G[32*33+32] + zw2*inv_var;
            out[b] = 0.5f*(ld - trace);
        }
    }
}

// ----------------------------------------------------------------------------
extern "C" void kernel_launch(void* const* d_in, const int* in_sizes, int n_in,
                              void* d_out, int out_size){
    (void)n_in; (void)out_size;
    InPtrs P;
    const float* L; const float* lam;
    if (in_sizes[0] > 1000000){
        // alphabetical: L, lam, w0..w4, z0..z4
        L   = (const float*)d_in[0];
        lam = (const float*)d_in[1];
        for (int l=0;l<5;++l){ P.w[l] = (const float*)d_in[2+l]; P.z[l] = (const float*)d_in[7+l]; }
    } else if (in_sizes[2] == 6144){
        // grouped: z0..z4, w0..w4, L, lam
        for (int l=0;l<5;++l){ P.z[l] = (const float*)d_in[l]; P.w[l] = (const float*)d_in[5+l]; }
        L   = (const float*)d_in[10];
        lam = (const float*)d_in[11];
    } else {
        // dict insertion order: z0,w0,z1,w1,...,L,lam
        for (int l=0;l<5;++l){ P.z[l] = (const float*)d_in[2*l]; P.w[l] = (const float*)d_in[2*l+1]; }
        L   = (const float*)d_in[10];
        lam = (const float*)d_in[11];
    }
    float* out = (float*)d_out;

    static int smem_set = 0;
    if (!smem_set){
        cudaFuncSetAttribute(k_main, cudaFuncAttributeMaxDynamicSharedMemorySize, SMEM_MAIN);
        smem_set = 1;
    }

    dim3 tA(32,32), gA(9,9,NM);
    k_prepA<<<gA, tA>>>(L);
    k_spyr<<<NM, 256>>>(lam);
    k_dft<<<dim3(CT, NB, 2), 128>>>(P);
    k_main<<<dim3(NM, NB), 256, SMEM_MAIN>>>();
    k_gram<<<dim3(NSEG, NB), 256>>>();
    k_reduce<<<(NB*1089 + 255)/256, 256>>>();
    k_final<<<NB, 256>>>(out);
}

// round 7
// speedup vs baseline: 3.2198x; 1.2832x over previous
#include <cuda_runtime.h>
#include <cuda_bf16.h>
#include <math.h>

#define NB 4
#define NM 32
#define CT 282
#define CT2 (CT*CT)
#define KTOT 24576          // 2 * 12288 floats per Gram row
#define SEG 256
#define NSEG 96
#define EPSR 1e-3f

#define SXP_N 16008         // X-pyramid complex elements per (b,m)
#define SC_N  3720          // C-table complex elements per (b,m)
// sXp + sC (float2) + sS (1364 f) + sU (3072 f)
#define SMEM_MAIN ((SXP_N + SC_N) * 8 + (1364 + 3072) * 4)   // 175568 bytes

// per-level constants
__constant__ int c_h[5]     = {2,4,8,16,32};
__constant__ int c_cnt[5]   = {192,48,24,12,6};
__constant__ int c_cbase[6] = {0,192,240,264,276,282};
__constant__ int c_OffC[5]  = {0,768,1536,3072,6144};   // complex offset of level block in Zh
__constant__ int c_LB[5]    = {0,768,1728,3744,7824};   // pyramid base per level
__constant__ int c_PS[5]    = {4,20,84,340,1364};       // pyramid size per channel of level
__constant__ int c_LO[5]    = {0,4,20,84,340};          // offset of level-l slice inside a pyramid
__constant__ int c_Cb[4]    = {0,360,1032,2184};        // C-table base per source level
__constant__ int c_ck0[5]   = {0,70,140,210,282};       // l0 fine-chunk channel bounds
__constant__ int c_ck1[3]   = {192,237,282};            // l1 fine-chunk channel bounds

// dft job table: 42 jobs
__constant__ int jb_l[42]  = {0,0,0,0,0,0, 1,1,1,1,1,1, 2,2,2,2,2,2,2,2,2,2,2,2,
                              3,3,3,3,3,3,3,3,3,3,3,3, 4,4,4,4,4,4};
__constant__ int jb_c0[42] = {0,32,64,96,128,160, 0,8,16,24,32,40,
                              0,2,4,6,8,10,12,14,16,18,20,22,
                              0,1,2,3,4,5,6,7,8,9,10,11, 0,1,2,3,4,5};
__constant__ int jb_n[42]  = {32,32,32,32,32,32, 8,8,8,8,8,8, 2,2,2,2,2,2,2,2,2,2,2,2,
                              1,1,1,1,1,1,1,1,1,1,1,1, 1,1,1,1,1,1};

// scratch (device globals; no allocation)
__device__ float  d_A [NM*CT2];                    // A[m][d][c] = L[m,c,d]-L[m,d,c]
__device__ float  d_Spyr[NM*1364];                 // alias pyramid of s per mode
__device__ __align__(16) float2 d_Zh[NB*12288];    // per-level DFTs of z
__device__ __align__(16) float  d_V [(size_t)NB*33*KTOT]; // Gram rows (0..31 = U-hat, 32 = w-hat)
__device__ float  d_pG[(size_t)NB*NSEG*1089];      // partial Grams
__device__ float  d_G [NB*1089];                   // reduced Grams

struct InPtrs { const float* z[5]; const float* w[5]; };

__device__ __forceinline__ int lvl_of(int c){
    return (c<192)?0:(c<240)?1:(c<264)?2:(c<276)?3:4;
}

// ---------------------------------------------------------------- A = L^T - L
__global__ void k_prepA(const float* __restrict__ L){
    __shared__ float Ta[32][33];
    int m  = blockIdx.z;
    int c0 = blockIdx.x*32, d0 = blockIdx.y*32;
    int tx = threadIdx.x, ty = threadIdx.y;
    const float* Lm = L + (size_t)m*CT2;
    int ci = c0+ty, dj = d0+tx;
    Ta[ty][tx] = (ci<CT && dj<CT) ? Lm[ci*CT + dj] : 0.f;
    __syncthreads();
    int di = d0+ty, cj = c0+tx;
    if (di<CT && cj<CT){
        d_A[((size_t)m*CT + di)*CT + cj] = Ta[tx][ty] - Lm[di*CT + cj];
    }
}

// ------------------------------------------------------- s and its alias pyramid
__global__ void k_spyr(const float* __restrict__ lam){
    __shared__ float sA[1024];
    __shared__ float sB[256];
    int m = blockIdx.x;
    int tid = threadIdx.x;          // 256
    const float* lm = lam + m*1024;
    for (int t=tid; t<1024; t+=256){
        int p = t>>5, q = t&31;
        float v = lm[t] - lm[(((32-p)&31)<<5) + ((32-q)&31)];
        sA[t] = v;
        d_Spyr[m*1364 + 340 + t] = v;
    }
    float* src = sA; float* dst = sB;
    int hs = 32;
    for (int k=0; k<4; ++k){
        __syncthreads();
        int hn = hs>>1;
        int off = c_LO[3-k];        // 84,20,4,0
        for (int t=tid; t<hn*hn; t+=256){
            int p = t/hn, q = t-p*hn;
            float v = src[p*hs+q] + src[(p+hn)*hs+q]
                    + src[p*hs+q+hn] + src[(p+hn)*hs+q+hn];
            dst[t] = v;
            d_Spyr[m*1364 + off + t] = v;
        }
        float* tmp = src; src = dst; dst = tmp;
        hs = hn;
    }
}

// ----------------------- batched small 2D DFTs of z (and w -> V row 32)
__global__ void __launch_bounds__(256) k_dft(InPtrs P){
    __shared__ float sIn[1024];
    __shared__ float tRe[1024];
    __shared__ float tIm[1024];
    __shared__ float2 tw[32];
    int j = blockIdx.x, b = blockIdx.y, isw = blockIdx.z;
    int l = jb_l[j];
    int h = c_h[l], hm = h-1;
    int lh = 31 - __clz(h);
    int lh2 = 2*lh;
    int h2 = h*h;
    int c0 = jb_c0[j], nch = jb_n[j];
    int npts = nch*h2;
    const float* in = (isw ? P.w[l] : P.z[l]) + (size_t)(b*c_cnt[l] + c0)*h2;
    int tid = threadIdx.x;
    if (tid < h){
        float sn, cn; __sincosf(-6.283185307179586f*(float)tid/(float)h, &sn, &cn);
        tw[tid] = make_float2(cn, sn);
    }
    for (int t=tid; t<npts; t+=256) sIn[t] = in[t];
    __syncthreads();
    for (int t=tid; t<npts; t+=256){
        int ch = t>>lh2;
        int pt = t & (h2-1);
        int p = pt>>lh, x = pt&hm;
        const float* base = sIn + (ch<<lh2) + x;
        float ar=0.f, ai=0.f;
        for (int y=0; y<h; ++y){
            float2 e = tw[(p*y)&hm];
            float v = base[y<<lh];
            ar += v*e.x; ai += v*e.y;
        }
        tRe[t]=ar; tIm[t]=ai;
    }
    __syncthreads();
    float inv = 1.0f/(float)h;
    float* vrow = d_V + ((size_t)(b*33+32))*KTOT;
    for (int t=tid; t<npts; t+=256){
        int ch = t>>lh2;
        int pt = t & (h2-1);
        int p = pt>>lh, q = pt&hm;
        const float* bR = tRe + (ch<<lh2) + (p<<lh);
        const float* bI = tIm + (ch<<lh2) + (p<<lh);
        float ar=0.f, ai=0.f;
        for (int x=0; x<h; ++x){
            float2 e = tw[(q*x)&hm];
            float re = bR[x], im = bI[x];
            ar += re*e.x - im*e.y;
            ai += re*e.y + im*e.x;
        }
        int kk = c_OffC[l] + (c0<<lh2) + t;
        if (!isw){
            d_Zh[b*12288 + kk] = make_float2(ar, ai);
        } else {
            vrow[2*kk  ] =  ai*inv;
            vrow[2*kk+1] = -ar*inv;
        }
    }
}

// ---------------- fine accumulation over channel range [lo,hi) at output level l
__device__ __forceinline__ void fine_acc(const float2* __restrict__ sXp,
                                         const float* __restrict__ A0,
                                         const float* __restrict__ A1,
                                         int l, int k0, int lo, int hi, float* ac){
    for (int lc=0; lc<5; ++lc){
        int a = lo > c_cbase[lc] ? lo : c_cbase[lc];
        int e = hi < c_cbase[lc+1] ? hi : c_cbase[lc+1];
        if (a >= e) continue;
        int ps = c_PS[lc];
        const float2* xp = sXp + c_LB[lc] + ps*(a - c_cbase[lc]) + c_LO[l] + k0;
        for (int c=a; c<e; ++c){
            float a0 = __ldg(A0 + c);
            float a1 = __ldg(A1 + c);
            float4 x01 = *(const float4*)(xp);
            float4 x23 = *(const float4*)(xp+2);
            ac[0] += a0*x01.x; ac[1] += a0*x01.y;
            ac[2] += a0*x01.z; ac[3] += a0*x01.w;
            ac[4] += a0*x23.x; ac[5] += a0*x23.y;
            ac[6] += a0*x23.z; ac[7] += a0*x23.w;
            ac[8] += a1*x01.x; ac[9] += a1*x01.y;
            ac[10]+= a1*x01.z; ac[11]+= a1*x01.w;
            ac[12]+= a1*x23.x; ac[13]+= a1*x23.y;
            ac[14]+= a1*x23.z; ac[15]+= a1*x23.w;
            xp += ps;
        }
    }
}

// ====================== fused per-(b,m) vector-field kernel ======================
__global__ void __launch_bounds__(512) k_main(){
    extern __shared__ float smraw[];
    float2* sXp = (float2*)smraw;              // [SXP_N]
    float2* sC  = sXp + SXP_N;                 // [SC_N]
    float*  sS  = (float*)(sC + SC_N);         // [1364]
    float*  sU  = sS + 1364;                   // [3072] level-0/1 U accumulators
    int m = blockIdx.x, b = blockIdx.y;
    int tid = threadIdx.x;

    for (int t=tid; t<1364; t+=512) sS[t] = d_Spyr[m*1364 + t];
    for (int t=tid; t<3072; t+=512) sU[t] = 0.f;
    for (int t=tid; t<720;  t+=512) ((float*)sC)[t] = 0.f;   // ls=0 C region (atomic)
    __syncthreads();

    const float2* Zb = d_Zh + b*12288;

    // ---- phase 1a: finest slices  sXp = S (x) Zh
    for (int f=tid; f<12288; f+=512){
        int l, rel;
        if (f<768){l=0;rel=f;} else if (f<1536){l=1;rel=f-768;}
        else if (f<3072){l=2;rel=f-1536;} else if (f<6144){l=3;rel=f-3072;}
        else {l=4;rel=f-6144;}
        int h2 = c_h[l]*c_h[l];
        int dl = rel/h2, pt = rel-dl*h2;
        float s = sS[c_LO[l]+pt];
        float2 z = Zb[f];
        sXp[c_LB[l] + c_PS[l]*dl + c_LO[l] + pt] = make_float2(s*z.x, s*z.y);
    }
    __syncthreads();

    // ---- phase 1b: alias pyramid, 4 steps
    for (int step=1; step<=4; ++step){
        for (int lc=step; lc<=4; ++lc){
            int lt = lc-step;
            int hn = c_h[lt], hsrc = hn*2, hh = hn*hn;
            int n = c_cnt[lc]*hh;
            for (int t=tid; t<n; t+=512){
                int dl = t/hh, pt = t-dl*hh;
                int p = pt/hn, q = pt-p*hn;
                float2* bch = sXp + c_LB[lc] + c_PS[lc]*dl;
                const float2* src = bch + c_LO[lt+1];
                float2 a0=src[p*hsrc+q],    a1=src[(p+hn)*hsrc+q];
                float2 a2=src[p*hsrc+q+hn], a3=src[(p+hn)*hsrc+q+hn];
                bch[c_LO[lt]+pt] = make_float2(a0.x+a1.x+a2.x+a3.x, a0.y+a1.y+a2.y+a3.y);
            }
        }
        __syncthreads();
    }

    // ---- phase 2: coarse residue table  C[ls][di][r] = sum_c A[d,c] Zh_c[r]
    // items: ls0 chunked 90*3=270 @64ch, ls1 168 @48, ls2 288 @24, ls3 384 @12 -> 1110
    for (int it=tid; it<1110; it+=512){
        int ls, di, r0, clo, chi, hh;
        float2* Cp; bool atom;
        if (it < 270){
            ls=0; di=it/3; int chunk=it-3*di;
            r0=0; clo=chunk*64; chi=clo+64; hh=4;
            Cp = sC + di*4; atom=true;
        } else if (it < 438){
            ls=1; int t2=it-270; di=t2>>2; int rt=t2&3; r0=rt*4;
            clo=0; chi=48; hh=16; Cp = sC + 360 + di*16 + r0; atom=false;
        } else if (it < 726){
            ls=2; int t2=it-438; di=t2>>4; int rt=t2&15; r0=rt*4;
            clo=0; chi=24; hh=64; Cp = sC + 1032 + di*64 + r0; atom=false;
        } else {
            ls=3; int t2=it-726; di=t2>>6; int rt=t2&63; r0=rt*4;
            clo=0; chi=12; hh=256; Cp = sC + 2184 + di*256 + r0; atom=false;
        }
        int dg = c_cbase[ls+1] + di;
        const float* Ar = d_A + ((size_t)m*CT + dg)*CT + c_cbase[ls];
        const float2* Zp = Zb + c_OffC[ls] + clo*hh + r0;
        float xr0=0,xi0=0,xr1=0,xi1=0,xr2=0,xi2=0,xr3=0,xi3=0;
        for (int c=clo; c<chi; ++c){
            float a = __ldg(Ar + c);
            float4 z01 = __ldg((const float4*)(Zp));
            float4 z23 = __ldg((const float4*)(Zp+2));
            xr0 += a*z01.x; xi0 += a*z01.y;
            xr1 += a*z01.z; xi1 += a*z01.w;
            xr2 += a*z23.x; xi2 += a*z23.y;
            xr3 += a*z23.z; xi3 += a*z23.w;
            Zp += hh;
        }
        if (atom){
            float* f = (float*)Cp;
            atomicAdd(f+0, xr0); atomicAdd(f+1, xi0);
            atomicAdd(f+2, xr1); atomicAdd(f+3, xi1);
            atomicAdd(f+4, xr2); atomicAdd(f+5, xi2);
            atomicAdd(f+6, xr3); atomicAdd(f+7, xi3);
        } else {
            Cp[0]=make_float2(xr0,xi0); Cp[1]=make_float2(xr1,xi1);
            Cp[2]=make_float2(xr2,xi2); Cp[3]=make_float2(xr3,xi3);
        }
    }
    __syncthreads();

    // ---- phase 3a: init sU level-1 part with s * C0 lookup (level-0 part stays 0)
    for (int t=tid; t<768; t+=512){
        int d1 = t>>4, k = t&15;
        int p = k>>2, q = k&3;
        int r = (p&1)*2 + (q&1);
        float s = sS[4 + k];
        float2 cv = sC[d1*4 + r];
        sU[1536 + 2*t    ] = s*cv.x;
        sU[1536 + 2*t + 1] = s*cv.y;
    }
    __syncthreads();

    // ---- phase 3: mixing. items:
    // [0,384)    l0: 96 dp x 4 chunks           (atomic into sU)
    // [384,576)  l1: 24 dp x 4 kt x 2 chunks    (atomic into sU)
    // [576,768)  l2: 12 dp x 16 kt              (direct)
    // [768,1152) l3: 6 dp x 64 kt               (direct)
    // [1152,1920)l4: 3 dp x 256 kt              (direct)
    float* vbase = d_V + ((size_t)(b*33+m))*KTOT;
    for (int it=tid; it<1920; it+=512){
        float ac[16];
        #pragma unroll
        for (int j=0;j<16;++j) ac[j]=0.f;

        if (it < 384){
            int dp = it>>2, chunk = it&3;
            int d0 = 2*dp;
            const float* A0 = d_A + ((size_t)m*CT + d0)*CT;
            fine_acc(sXp, A0, A0+CT, 0, 0, c_ck0[chunk], c_ck0[chunk+1], ac);
            float* u0 = sU + d0*8;
            #pragma unroll
            for (int j=0;j<8;++j) atomicAdd(u0+j, ac[j]);
            float* u1 = u0 + 8;
            #pragma unroll
            for (int j=0;j<8;++j) atomicAdd(u1+j, ac[8+j]);
        } else if (it < 576){
            int jj = it-384;
            int dp = jj>>3, kt = (jj>>1)&3, chunk = jj&1;
            int d0 = 192 + 2*dp, k0 = kt*4;
            const float* A0 = d_A + ((size_t)m*CT + d0)*CT;
            fine_acc(sXp, A0, A0+CT, 1, k0, c_ck1[chunk], c_ck1[chunk+1], ac);
            float* u0 = sU + 1536 + (d0-192)*32 + k0*2;
            #pragma unroll
            for (int j=0;j<8;++j) atomicAdd(u0+j, ac[j]);
            float* u1 = u0 + 32;
            #pragma unroll
            for (int j=0;j<8;++j) atomicAdd(u1+j, ac[8+j]);
        } else {
            int l, rem;
            if (it<768){l=2; rem=it-576;} else if (it<1152){l=3; rem=it-768;}
            else {l=4; rem=it-1152;}
            int h=c_h[l], h2=h*h, nkt=h2>>2, hm=h-1;
            int lh = 31 - __clz(h);
            int dp = rem/nkt, kt = rem-dp*nkt;
            int k0 = kt*4;
            int d0 = c_cbase[l] + 2*dp;

            // coarse init
            int pp[4], qq[4];
            #pragma unroll
            for (int j=0;j<4;++j){ int k=k0+j; pp[j]=k>>lh; qq[j]=k&hm; }
            for (int ls=0; ls<l; ++ls){
                int hs=c_h[ls], hh=hs*hs, hsm=hs-1;
                const float2* Cp = sC + c_Cb[ls] + (d0 - c_cbase[ls+1])*hh;
                #pragma unroll
                for (int j=0;j<4;++j){
                    int r = (pp[j]&hsm)*hs + (qq[j]&hsm);
                    float2 v0 = Cp[r], v1 = Cp[hh+r];
                    ac[2*j]   += v0.x; ac[2*j+1] += v0.y;
                    ac[8+2*j] += v1.x; ac[8+2*j+1]+= v1.y;
                }
            }
            const float* Sl = sS + c_LO[l] + k0;
            #pragma unroll
            for (int j=0;j<4;++j){
                float s = Sl[j];
                ac[2*j]   *= s; ac[2*j+1] *= s;
                ac[8+2*j] *= s; ac[8+2*j+1]*= s;
            }

            const float* A0 = d_A + ((size_t)m*CT + d0)*CT;
            fine_acc(sXp, A0, A0+CT, l, k0, c_cbase[l], 282, ac);

            float scale = (float)h * (1.0f/1024.0f);
            {
                float* vp = vbase + 2*(c_OffC[l] + (2*dp + d0 - d0)*0 + d0*h2 + k0) - 2*c_cbase[l]*h2;
                // (simplify below; compute directly)
            }
            float* vp0 = vbase + 2*(c_OffC[l] + (d0 - c_cbase[l])*h2 + k0);
            float* vp1 = vp0 + 2*h2;
            float4 o0, o1;
            o0.x = scale*ac[0]; o0.y = scale*ac[1]; o0.z = scale*ac[2]; o0.w = scale*ac[3];
            o1.x = scale*ac[4]; o1.y = scale*ac[5]; o1.z = scale*ac[6]; o1.w = scale*ac[7];
            *(float4*)(vp0)   = o0;
            *(float4*)(vp0+4) = o1;
            o0.x = scale*ac[8]; o0.y = scale*ac[9]; o0.z = scale*ac[10]; o0.w = scale*ac[11];
            o1.x = scale*ac[12]; o1.y = scale*ac[13]; o1.z = scale*ac[14]; o1.w = scale*ac[15];
            *(float4*)(vp1)   = o0;
            *(float4*)(vp1+4) = o1;
        }
    }
    __syncthreads();

    // ---- phase 3d: write out levels 0-1 from sU (contiguous, matches d_V layout)
    for (int t=tid; t<3072; t+=512){
        float sc = (t<1536) ? (2.0f/1024.0f) : (4.0f/1024.0f);
        vbase[t] = sc * sU[t];
    }
}

// ------------------------------------------------- segmented 33x33 Gram, triangular 2x2 tiles
__global__ void __launch_bounds__(256) k_gram(){
    __shared__ float sm[34*257];
    int seg = blockIdx.x, b = blockIdx.y;
    int tid = threadIdx.x;          // 256
    const float* Vb = d_V + (size_t)b*33*KTOT + seg*SEG;
    for (int r=0; r<33; ++r) sm[r*257+tid] = Vb[(size_t)r*KTOT + tid];
    sm[33*257+tid] = 0.f;
    __syncthreads();
    float* out = d_pG + ((size_t)(b*NSEG+seg))*1089;
    if (tid < 153){
        int t = tid;
        int ti = (int)((35.0f - sqrtf(1225.0f - 8.0f*(float)t)) * 0.5f);
        if (ti > 16) ti = 16; if (ti < 0) ti = 0;
        int off = 17*ti - (ti*(ti-1))/2;
        while (off > t){ ti--; off = 17*ti - (ti*(ti-1))/2; }
        while (off + (17-ti) <= t){ off += 17-ti; ti++; }
        int tj = ti + (t - off);
        const float* r0 = sm + (2*ti)*257;
        const float* r1 = r0 + 257;
        const float* q0 = sm + (2*tj)*257;
        const float* q1 = q0 + 257;
        float a00=0,a01=0,a10=0,a11=0;
        #pragma unroll 4
        for (int k=0; k<SEG; ++k){
            float x0=r0[k], x1=r1[k], y0=q0[k], y1=q1[k];
            a00 += x0*y0; a01 += x0*y1;
            a10 += x1*y0; a11 += x1*y1;
        }
        int i0=2*ti, j0=2*tj;
        int i1=i0+1, j1=j0+1;
        // direct writes
        out[i0*33+j0] = a00;
        if (j1<33) out[i0*33+j1] = a01;
        if (i1<33) out[i1*33+j0] = a10;
        if (i1<33 && j1<33) out[i1*33+j1] = a11;
        // mirrors
        out[j0*33+i0] = a00;
        if (j1<33) out[j1*33+i0] = a01;
        if (i1<33) out[j0*33+i1] = a10;
        if (i1<33 && j1<33) out[j1*33+i1] = a11;
    }
}

// ------------------------------------------------- parallel partial-Gram reduce
__global__ void k_reduce(){
    int idx = blockIdx.x*256 + threadIdx.x;
    if (idx >= NB*1089) return;
    int b = idx/1089, pair = idx - 1089*b;
    float acc = 0.f;
    #pragma unroll 8
    for (int s=0; s<NSEG; ++s) acc += d_pG[((size_t)(b*NSEG+s))*1089 + pair];
    d_G[idx] = acc;
}

// ------------------------------------------------- stats + Cholesky + logdet
__global__ void k_final(float* __restrict__ out){
    __shared__ float G[1089];
    __shared__ float Mch[32][33];
    __shared__ float sc0;
    int b = blockIdx.x;
    int tid = threadIdx.x;          // 256
    for (int pair=tid; pair<1089; pair+=256) G[pair] = d_G[b*1089 + pair];
    __syncthreads();
    if (tid < 32){
        float dg = G[tid*33+tid];
        for (int o=16;o>0;o>>=1) dg += __shfl_down_sync(0xffffffffu, dg, o);
        if (tid==0){
            float var = dg * (1.0f/32.0f);
            if (var < 1e-6f) var = 1e-6f;
            sc0 = var;
        }
    }
    __syncthreads();
    float var = sc0;
    float inv_var = 1.0f/var;
    for (int t=tid; t<1024; t+=256){
        int i = t>>5, j = t&31;
        Mch[i][j] = G[i*33+j]*inv_var + ((i==j)?EPSR:0.f);
    }
    __syncthreads();
    for (int k=0; k<32; ++k){
        if (tid==0) Mch[k][k] = sqrtf(Mch[k][k]);
        __syncthreads();
        if (tid>k && tid<32) Mch[tid][k] /= Mch[k][k];
        __syncthreads();
        if (tid>k && tid<32){
            float lik = Mch[tid][k];
            for (int j=k+1; j<=tid; ++j) Mch[tid][j] -= lik*Mch[j][k];
        }
        __syncthreads();
    }
    if (tid < 32){
        float ld  = 2.0f*logf(Mch[tid][tid]);
        float zw  = G[tid*33+32];
        float zw2 = zw*zw;
        for (int o=16;o>0;o>>=1){
            ld  += __shfl_down_sync(0xffffffffu, ld,  o);
            zw2 += __shfl_down_sync(0xffffffffu, zw2, o);
        }
        if (tid==0){
            float trace = EPSR*G[32*33+32] + zw2*inv_var;
            out[b] = 0.5f*(ld - trace);
        }
    }
}

// ----------------------------------------------------------------------------
extern "C" void kernel_launch(void* const* d_in, const int* in_sizes, int n_in,
                              void* d_out, int out_size){
    (void)n_in; (void)out_size;
    InPtrs P;
    const float* L; const float* lam;
    if (in_sizes[0] > 1000000){
        // alphabetical: L, lam, w0..w4, z0..z4
        L   = (const float*)d_in[0];
        lam = (const float*)d_in[1];
        for (int l=0;l<5;++l){ P.w[l] = (const float*)d_in[2+l]; P.z[l] = (const float*)d_in[7+l]; }
    } else if (in_sizes[2] == 6144){
        // grouped: z0..z4, w0..w4, L, lam
        for (int l=0;l<5;++l){ P.z[l] = (const float*)d_in[l]; P.w[l] = (const float*)d_in[5+l]; }
        L   = (const float*)d_in[10];
        lam = (const float*)d_in[11];
    } else {
        // dict insertion order: z0,w0,z1,w1,...,L,lam
        for (int l=0;l<5;++l){ P.z[l] = (const float*)d_in[2*l]; P.w[l] = (const float*)d_in[2*l+1]; }
        L   = (const float*)d_in[10];
        lam = (const float*)d_in[11];
    }
    float* out = (float*)d_out;

    static int smem_set = 0;
    if (!smem_set){
        cudaFuncSetAttribute(k_main, cudaFuncAttributeMaxDynamicSharedMemorySize, SMEM_MAIN);
        smem_set = 1;
    }

    dim3 tA(32,32), gA(9,9,NM);
    k_prepA<<<gA, tA>>>(L);
    k_spyr<<<NM, 256>>>(lam);
    k_dft<<<dim3(42, NB, 2), 256>>>(P);
    k_main<<<dim3(NM, NB), 512, SMEM_MAIN>>>();
    k_gram<<<dim3(NSEG, NB), 256>>>();
    k_reduce<<<(NB*1089 + 255)/256, 256>>>();
    k_final<<<NB, 256>>>(out);
}